// round 2
// baseline (speedup 1.0000x reference)
#include <cuda_runtime.h>
#include <math.h>

// ---------------------------------------------------------------------------
// Problem constants
//   x:      (4, 96, 96, 192)  -> tokens = 36864
//   qkv:    tokens x 576      (per 192-chunk g: [q(2x32) | k(2x32) | v(2x32)])
//   att:    tokens x 192      (concat of 3 groups x 2 heads x 32)
//   out:    tokens x 192
// ---------------------------------------------------------------------------
#define TOKENS (4 * 96 * 96)

__device__ float g_qkv[(size_t)TOKENS * 576]; // 85 MB scratch
__device__ float g_att[(size_t)TOKENS * 192]; // 28 MB scratch

// ---------------------------------------------------------------------------
// Tiled SIMT fp32 GEMM:  C[M,N] = A[M,K] @ B[K,N] + bias[N]
// BM=128, BN=64, BK=16, 256 threads, 8x4 microtile per thread.
// Requires M % 128 == 0, N % 64 == 0, K % 16 == 0 (true here).
// ---------------------------------------------------------------------------
__global__ void __launch_bounds__(256, 2) gemm_bias_kernel(
    const float* __restrict__ A, const float* __restrict__ B,
    const float* __restrict__ bias, float* __restrict__ C,
    int M, int N, int K)
{
    constexpr int BM = 128, BN = 64, BK = 16;
    __shared__ float As[BK][BM + 4]; // +4 pad: cheap conflict reduction on store
    __shared__ float Bs[BK][BN];

    const int tid = threadIdx.x;
    const int tx  = tid & 15;  // N direction (4 cols each)
    const int ty  = tid >> 4;  // M direction (8 rows each)
    const int mi0 = blockIdx.x * BM;
    const int nj0 = blockIdx.y * BN;

    float acc[8][4];
#pragma unroll
    for (int r = 0; r < 8; ++r)
#pragma unroll
        for (int j = 0; j < 4; ++j) acc[r][j] = 0.f;

    for (int k0 = 0; k0 < K; k0 += BK) {
        // Load A tile (128 rows x 16 cols) = 512 float4, 2 per thread,
        // stored transposed into As[k][m].
#pragma unroll
        for (int i = 0; i < 2; ++i) {
            int idx = tid + i * 256;
            int row = idx >> 2;
            int qq  = idx & 3;
            float4 a4 = *(const float4*)&A[(size_t)(mi0 + row) * K + k0 + qq * 4];
            As[qq * 4 + 0][row] = a4.x;
            As[qq * 4 + 1][row] = a4.y;
            As[qq * 4 + 2][row] = a4.z;
            As[qq * 4 + 3][row] = a4.w;
        }
        // Load B tile (16 rows x 64 cols) = 256 float4, 1 per thread.
        {
            int row = tid >> 4;
            int qq  = tid & 15;
            *(float4*)&Bs[row][qq * 4] =
                *(const float4*)&B[(size_t)(k0 + row) * N + nj0 + qq * 4];
        }
        __syncthreads();

#pragma unroll
        for (int kk = 0; kk < BK; ++kk) {
            float af[8], bf[4];
            *(float4*)&af[0] = *(const float4*)&As[kk][ty * 8];
            *(float4*)&af[4] = *(const float4*)&As[kk][ty * 8 + 4];
            *(float4*)&bf[0] = *(const float4*)&Bs[kk][tx * 4];
#pragma unroll
            for (int r = 0; r < 8; ++r)
#pragma unroll
                for (int j = 0; j < 4; ++j)
                    acc[r][j] = fmaf(af[r], bf[j], acc[r][j]);
        }
        __syncthreads();
    }

    float4 bv = *(const float4*)&bias[nj0 + tx * 4];
#pragma unroll
    for (int r = 0; r < 8; ++r) {
        float4 o;
        o.x = acc[r][0] + bv.x;
        o.y = acc[r][1] + bv.y;
        o.z = acc[r][2] + bv.z;
        o.w = acc[r][3] + bv.w;
        *(float4*)&C[(size_t)(mi0 + ty * 8 + r) * N + nj0 + tx * 4] = o;
    }
}

// ---------------------------------------------------------------------------
// Neighborhood attention 2D, window KS x KS, head_dim 32.
// One block = 16x16 pixel tile for a single (batch, group, head).
// K/V halos staged in smem (pixel stride padded to 36 floats -> conflict-free
// LDS.128 across a half-warp of adjacent pixels). Online softmax per thread.
// ---------------------------------------------------------------------------
template <int KS>
__global__ void __launch_bounds__(256, 1) na2d_kernel(
    const float* __restrict__ qkv, float* __restrict__ att, int g)
{
    constexpr int HS   = 16 + KS - 1; // halo side
    constexpr int PSTR = 36;          // padded floats per halo pixel
    extern __shared__ float sm[];
    float* Ksm = sm;
    float* Vsm = sm + HS * HS * PSTR;

    const int tid = threadIdx.x;
    const int b   = blockIdx.z >> 1;
    const int h   = blockIdx.z & 1;
    const int ti0 = blockIdx.y * 16;
    const int tj0 = blockIdx.x * 16;

    const int hi0 = min(max(ti0 - KS / 2, 0), 96 - KS);
    const int hj0 = min(max(tj0 - KS / 2, 0), 96 - KS);

    const int cbq = g * 192 + h * 32;
    const int cbk = cbq + 64;
    const int cbv = cbq + 128;
    const size_t bbase = (size_t)b * 96 * 96 * 576;

    // Cooperative halo load (K and V), float4-granular, coalesced in gmem.
    for (int idx = tid; idx < HS * HS * 8; idx += 256) {
        int p  = idx >> 3;
        int c4 = idx & 7;
        int pi = min(hi0 + p / HS, 95); // clamped rows/cols are never read
        int pj = min(hj0 + p % HS, 95);
        size_t src = bbase + (size_t)(pi * 96 + pj) * 576;
        *(float4*)&Ksm[p * PSTR + c4 * 4] = *(const float4*)&qkv[src + cbk + c4 * 4];
        *(float4*)&Vsm[p * PSTR + c4 * 4] = *(const float4*)&qkv[src + cbv + c4 * 4];
    }

    // Per-thread query (pre-scaled).
    const int x  = tid & 15;
    const int y  = tid >> 4;
    const int pi = ti0 + y;
    const int pj = tj0 + x;
    float q[32];
    {
        const float scale = 0.17677669529663687f; // 32^-0.5
        const float* qp = &qkv[bbase + (size_t)(pi * 96 + pj) * 576 + cbq];
#pragma unroll
        for (int c4 = 0; c4 < 8; ++c4) {
            float4 v = *(const float4*)&qp[c4 * 4];
            q[c4 * 4 + 0] = v.x * scale;
            q[c4 * 4 + 1] = v.y * scale;
            q[c4 * 4 + 2] = v.z * scale;
            q[c4 * 4 + 3] = v.w * scale;
        }
    }
    __syncthreads();

    // Window offsets inside the halo for this pixel.
    const int si = min(max(pi - KS / 2, 0), 96 - KS) - hi0;
    const int sj = min(max(pj - KS / 2, 0), 96 - KS) - hj0;

    float m = -1e30f, l = 0.f;
    float acc[32];
#pragma unroll
    for (int c = 0; c < 32; ++c) acc[c] = 0.f;

    for (int a = 0; a < KS; ++a) {
        const float* kr = &Ksm[((si + a) * HS + sj) * PSTR];
        const float* vr = &Vsm[((si + a) * HS + sj) * PSTR];
#pragma unroll 1
        for (int bb = 0; bb < KS; ++bb) {
            const float* kv = kr + bb * PSTR;
            float s = 0.f;
#pragma unroll
            for (int c4 = 0; c4 < 8; ++c4) {
                float4 k4 = *(const float4*)&kv[c4 * 4];
                s = fmaf(q[c4 * 4 + 0], k4.x, s);
                s = fmaf(q[c4 * 4 + 1], k4.y, s);
                s = fmaf(q[c4 * 4 + 2], k4.z, s);
                s = fmaf(q[c4 * 4 + 3], k4.w, s);
            }
            float p;
            if (s > m) {
                float corr = __expf(m - s); // first iter: exp(-huge) -> 0
                l *= corr;
#pragma unroll
                for (int c = 0; c < 32; ++c) acc[c] *= corr;
                m = s;
                p = 1.0f;
            } else {
                p = __expf(s - m);
            }
            l += p;
            const float* vv = vr + bb * PSTR;
#pragma unroll
            for (int c4 = 0; c4 < 8; ++c4) {
                float4 v4 = *(const float4*)&vv[c4 * 4];
                acc[c4 * 4 + 0] = fmaf(p, v4.x, acc[c4 * 4 + 0]);
                acc[c4 * 4 + 1] = fmaf(p, v4.y, acc[c4 * 4 + 1]);
                acc[c4 * 4 + 2] = fmaf(p, v4.z, acc[c4 * 4 + 2]);
                acc[c4 * 4 + 3] = fmaf(p, v4.w, acc[c4 * 4 + 3]);
            }
        }
    }

    const float inv = 1.f / l;
    float* op = &att[((size_t)(b * 96 * 96) + pi * 96 + pj) * 192 + g * 64 + h * 32];
#pragma unroll
    for (int c4 = 0; c4 < 8; ++c4) {
        float4 o;
        o.x = acc[c4 * 4 + 0] * inv;
        o.y = acc[c4 * 4 + 1] * inv;
        o.z = acc[c4 * 4 + 2] * inv;
        o.w = acc[c4 * 4 + 3] * inv;
        *(float4*)&op[c4 * 4] = o;
    }
}

// ---------------------------------------------------------------------------
// kernel_launch
// inputs: x(36864x192), w_qkv(192x576), b_qkv(576), w_proj(192x192), b_proj(192)
// output: 36864x192 float32
// ---------------------------------------------------------------------------
extern "C" void kernel_launch(void* const* d_in, const int* in_sizes, int n_in,
                              void* d_out, int out_size)
{
    (void)in_sizes; (void)n_in; (void)out_size;
    const float* x      = (const float*)d_in[0];
    const float* w_qkv  = (const float*)d_in[1];
    const float* b_qkv  = (const float*)d_in[2];
    const float* w_proj = (const float*)d_in[3];
    const float* b_proj = (const float*)d_in[4];
    float* out = (float*)d_out;

    void* qkv_p = nullptr;
    void* att_p = nullptr;
    cudaGetSymbolAddress(&qkv_p, g_qkv);
    cudaGetSymbolAddress(&att_p, g_att);
    float* qkv = (float*)qkv_p;
    float* att = (float*)att_p;

    // Dynamic smem sizes: 2 halos * HS*HS*36 floats
    const int smem7  = 2 * 22 * 22 * 36 * 4; // 139,392 B
    const int smem9  = 2 * 24 * 24 * 36 * 4; // 165,888 B
    const int smem11 = 2 * 26 * 26 * 36 * 4; // 194,688 B
    cudaFuncSetAttribute(na2d_kernel<7>,  cudaFuncAttributeMaxDynamicSharedMemorySize, smem7);
    cudaFuncSetAttribute(na2d_kernel<9>,  cudaFuncAttributeMaxDynamicSharedMemorySize, smem9);
    cudaFuncSetAttribute(na2d_kernel<11>, cudaFuncAttributeMaxDynamicSharedMemorySize, smem11);

    // 1) QKV GEMM: (36864 x 192) @ (192 x 576)
    gemm_bias_kernel<<<dim3(TOKENS / 128, 576 / 64), 256>>>(
        x, w_qkv, b_qkv, qkv, TOKENS, 576, 192);

    // 2) Neighborhood attention, one launch per window size.
    dim3 agrid(6, 6, 4 * 2);
    na2d_kernel<7><<<agrid, 256, smem7>>>(qkv, att, 0);
    na2d_kernel<9><<<agrid, 256, smem9>>>(qkv, att, 1);
    na2d_kernel<11><<<agrid, 256, smem11>>>(qkv, att, 2);

    // 3) Projection GEMM: (36864 x 192) @ (192 x 192) -> d_out
    gemm_bias_kernel<<<dim3(TOKENS / 128, 192 / 64), 256>>>(
        att, w_proj, b_proj, out, TOKENS, 192, 192);
}